// round 3
// baseline (speedup 1.0000x reference)
#include <cuda_runtime.h>
#include <cstdint>

#define N_TEMPL 4
#define N_RES   768
#define NCH     64
#define N_BINS  40              // 39 real bins + 1 "no bin" (zero contribution)
#define N_AA    22
#define COMB_N  (N_BINS * N_AA) // 880 combined columns

// Combined gather table: comb[bin][aa_j][o] = W[o,bin] (0 if bin==39)
//                                           + W[o,40+aa_j] + W[o,87]
__device__ float g_comb[COMB_N * NCH];

__global__ void build_comb(const float* __restrict__ lw) {
    int idx = blockIdx.x * blockDim.x + threadIdx.x;   // < 880*64
    if (idx >= COMB_N * NCH) return;
    int o   = idx & 63;
    int c   = idx >> 6;
    int bin = c / N_AA;
    int aj  = c - bin * N_AA;
    float v = lw[o * 88 + 40 + aj] + lw[o * 88 + 87];
    if (bin < 39) v += lw[o * 88 + bin];
    g_comb[idx] = v;
}

// smem: sData 768*16 = 12288 B + frame constants ≈ 12.4 KB
__global__ __launch_bounds__(256) void tpe_kernel(
    const float* __restrict__ pos,      // [T,768,37,3]
    const float* __restrict__ pb,       // [T,768,3]
    const float* __restrict__ pbm,      // [T,768]
    const float* __restrict__ aam,      // [T,768,37]
    const int*   __restrict__ aatype,   // [T,768]
    const float* __restrict__ lw,       // [64,88] row-major (o-major)
    const float* __restrict__ lb,       // [64]
    float* __restrict__ out)            // [T,768,768,64]
{
    __shared__ float4 sData[N_RES];     // uvx, uvy, uvz, packed(bin*22+aa | pb2<<10 | fm2<<11)
    __shared__ float  sM[9];
    __shared__ float  sCa[3];
    __shared__ float  sPb[3];
    __shared__ float  sPbmI;
    __shared__ float  sFmI;
    __shared__ int    sAaI;

    const float EPS = 1e-6f;
    const int t = blockIdx.x / N_RES;
    const int i = blockIdx.x % N_RES;
    const int tid = threadIdx.x;

    // ---------------- Phase 0: build rigid frame for residue i ----------------
    if (tid == 0) {
        const float* pr = pos + ((size_t)(t * N_RES + i) * 37) * 3;
        float nx0 = pr[0], nx1 = pr[1], nx2 = pr[2];     // N
        float ca0 = pr[3], ca1 = pr[4], ca2 = pr[5];     // CA
        float cc0 = pr[6], cc1 = pr[7], cc2 = pr[8];     // C
        float n0 = nx0 - ca0, n1 = nx1 - ca1, n2 = nx2 - ca2;
        float c0 = cc0 - ca0, c1v = cc1 - ca1, c2v = cc2 - ca2;

        float d2xy = c0 * c0 + c1v * c1v;
        float norm1 = sqrtf(EPS + d2xy);
        float s1 = -c1v / norm1, co1 = c0 / norm1;
        float norm2 = sqrtf(EPS + d2xy + c2v * c2v);
        float s2 = c2v / norm2, co2 = sqrtf(d2xy) / norm2;

        float r00 = co2 * co1, r01 = -co2 * s1, r02 = s2;
        float r10 = s1,        r11 = co1,       r12 = 0.0f;
        float r20 = -s2 * co1, r21 = s2 * s1,   r22 = co2;

        float nyp = r10 * n0 + r11 * n1 + r12 * n2;
        float nzp = r20 * n0 + r21 * n1 + r22 * n2;
        float norm3 = sqrtf(EPS + nyp * nyp + nzp * nzp);
        float sn = -nzp / norm3, cn = nyp / norm3;

        sM[0] = r00; sM[1] = r01; sM[2] = r02;
        sM[3] = cn * r10 - sn * r20; sM[4] = cn * r11 - sn * r21; sM[5] = cn * r12 - sn * r22;
        sM[6] = sn * r10 + cn * r20; sM[7] = sn * r11 + cn * r21; sM[8] = sn * r12 + cn * r22;

        sCa[0] = ca0; sCa[1] = ca1; sCa[2] = ca2;
        const float* pbi = pb + (size_t)(t * N_RES + i) * 3;
        sPb[0] = pbi[0]; sPb[1] = pbi[1]; sPb[2] = pbi[2];
        sPbmI = pbm[t * N_RES + i];
        const float* ami = aam + (size_t)(t * N_RES + i) * 37;
        sFmI = ami[0] * ami[1] * ami[2];
        sAaI = aatype[t * N_RES + i];
    }
    __syncthreads();

    // ---------------- Phase 1: per-j scalars ----------------------------------
    {
        const float m0 = sM[0], m1 = sM[1], m2 = sM[2];
        const float m3 = sM[3], m4 = sM[4], m5 = sM[5];
        const float m6 = sM[6], m7 = sM[7], m8 = sM[8];
        const float cai0 = sCa[0], cai1 = sCa[1], cai2 = sCa[2];
        const float pbi0 = sPb[0], pbi1 = sPb[1], pbi2 = sPb[2];
        const float pbmi = sPbmI, fmi = sFmI;

        for (int j = tid; j < N_RES; j += 256) {
            // distogram bin (match reference FP ordering)
            const float* pbj = pb + (size_t)(t * N_RES + j) * 3;
            float dx = __fadd_rn(pbi0, -pbj[0]);
            float dy = __fadd_rn(pbi1, -pbj[1]);
            float dz = __fadd_rn(pbi2, -pbj[2]);
            float dsq = __fadd_rn(__fadd_rn(__fmul_rn(dx, dx), __fmul_rn(dy, dy)),
                                  __fmul_rn(dz, dz));
            int k = (int)floorf((sqrtf(dsq) - 3.25f) * 0.8f);
            k = min(max(k, -1), 38);
            int bin = -1;
            int clo = max(k - 1, 0), chi = min(k + 1, 38);
            #pragma unroll
            for (int c = 0; c < 3; ++c) {
                int cand = clo + c;
                if (cand > chi) break;
                float lbv = 3.25f + (float)cand * 1.25f;  lbv = lbv * lbv;
                float ubv = (cand == 38) ? 1e8f
                           : (3.25f + (float)(cand + 1) * 1.25f) *
                             (3.25f + (float)(cand + 1) * 1.25f);
                if (dsq > lbv && dsq < ubv) { bin = cand; break; }
            }

            // rigid vec + unit vector
            const float* pj = pos + ((size_t)(t * N_RES + j) * 37 + 1) * 3; // CA_j
            float ddx = pj[0] - cai0, ddy = pj[1] - cai1, ddz = pj[2] - cai2;
            float rvx = m0 * ddx + m1 * ddy + m2 * ddz;
            float rvy = m3 * ddx + m4 * ddy + m5 * ddz;
            float rvz = m6 * ddx + m7 * ddy + m8 * ddz;
            float inv = 1.0f / sqrtf(EPS + (rvx * rvx + rvy * rvy + rvz * rvz));
            float uvx = rvx * inv, uvy = rvy * inv, uvz = rvz * inv;

            const float* amj = aam + (size_t)(t * N_RES + j) * 37;
            float fm2 = fmi * (amj[0] * amj[1] * amj[2]);
            float pb2 = pbmi * pbm[t * N_RES + j];

            int binCol = (bin < 0) ? 39 : bin;
            int packed = binCol * N_AA + aatype[t * N_RES + j];
            if (pb2 != 0.0f) packed |= 1 << 10;
            if (fm2 != 0.0f) packed |= 1 << 11;
            sData[j] = make_float4(uvx, uvy, uvz, __int_as_float(packed));
        }
    }
    __syncthreads();

    // ---------------- Phase 2: 16 threads x 4 channels per j ------------------
    const int oq = tid & 15;          // channel quad
    const int jl = tid >> 4;          // 16 j's per iteration
    const int ob = oq * 4;

    // per-thread constants for channels ob..ob+3 (L1/L2-cached direct loads)
    float4 rowb, w39v, w84v, w85v, w86v, bv;
    {
        int ai = sAaI;
        rowb = make_float4(__ldg(&lw[(ob + 0) * 88 + 62 + ai]),
                           __ldg(&lw[(ob + 1) * 88 + 62 + ai]),
                           __ldg(&lw[(ob + 2) * 88 + 62 + ai]),
                           __ldg(&lw[(ob + 3) * 88 + 62 + ai]));
        w39v = make_float4(__ldg(&lw[(ob + 0) * 88 + 39]), __ldg(&lw[(ob + 1) * 88 + 39]),
                           __ldg(&lw[(ob + 2) * 88 + 39]), __ldg(&lw[(ob + 3) * 88 + 39]));
        w84v = make_float4(__ldg(&lw[(ob + 0) * 88 + 84]), __ldg(&lw[(ob + 1) * 88 + 84]),
                           __ldg(&lw[(ob + 2) * 88 + 84]), __ldg(&lw[(ob + 3) * 88 + 84]));
        w85v = make_float4(__ldg(&lw[(ob + 0) * 88 + 85]), __ldg(&lw[(ob + 1) * 88 + 85]),
                           __ldg(&lw[(ob + 2) * 88 + 85]), __ldg(&lw[(ob + 3) * 88 + 85]));
        w86v = make_float4(__ldg(&lw[(ob + 0) * 88 + 86]), __ldg(&lw[(ob + 1) * 88 + 86]),
                           __ldg(&lw[(ob + 2) * 88 + 86]), __ldg(&lw[(ob + 3) * 88 + 86]));
        bv   = *(const float4*)&lb[ob];
    }

    float* orow = out + ((size_t)(t * N_RES + i) * N_RES) * NCH;

    #pragma unroll 4
    for (int jb = 0; jb < N_RES; jb += 16) {
        int j = jb + jl;
        float4 d = sData[j];
        int p = __float_as_int(d.w);

        const float4 cb = __ldg((const float4*)&g_comb[((p & 1023) << 6) + ob]);
        float pb2f = (p & (1 << 10)) ? 1.0f : 0.0f;
        float fm2f = (p & (1 << 11)) ? 1.0f : 0.0f;

        float4 r;
        {
            float s = rowb.x + cb.x;
            s = fmaf(pb2f, w39v.x, s);
            s = fmaf(d.x, w84v.x, s);
            s = fmaf(d.y, w85v.x, s);
            s = fmaf(d.z, w86v.x, s);
            r.x = fmaf(fm2f, s, bv.x);
        }
        {
            float s = rowb.y + cb.y;
            s = fmaf(pb2f, w39v.y, s);
            s = fmaf(d.x, w84v.y, s);
            s = fmaf(d.y, w85v.y, s);
            s = fmaf(d.z, w86v.y, s);
            r.y = fmaf(fm2f, s, bv.y);
        }
        {
            float s = rowb.z + cb.z;
            s = fmaf(pb2f, w39v.z, s);
            s = fmaf(d.x, w84v.z, s);
            s = fmaf(d.y, w85v.z, s);
            s = fmaf(d.z, w86v.z, s);
            r.z = fmaf(fm2f, s, bv.z);
        }
        {
            float s = rowb.w + cb.w;
            s = fmaf(pb2f, w39v.w, s);
            s = fmaf(d.x, w84v.w, s);
            s = fmaf(d.y, w85v.w, s);
            s = fmaf(d.z, w86v.w, s);
            r.w = fmaf(fm2f, s, bv.w);
        }

        *(float4*)&orow[(size_t)j * NCH + ob] = r;
    }
}

extern "C" void kernel_launch(void* const* d_in, const int* in_sizes, int n_in,
                              void* d_out, int out_size) {
    const float* pos    = (const float*)d_in[0];  // [4,768,37,3]
    const float* pb     = (const float*)d_in[1];  // [4,768,3]
    const float* pbmask = (const float*)d_in[2];  // [4,768]
    const float* aamask = (const float*)d_in[3];  // [4,768,37]
    const int*   aatype = (const int*)  d_in[4];  // [4,768]
    const float* lw     = (const float*)d_in[5];  // [64,88]
    const float* lb     = (const float*)d_in[6];  // [64]
    float* out = (float*)d_out;

    build_comb<<<(COMB_N * NCH + 255) / 256, 256>>>(lw);
    tpe_kernel<<<N_TEMPL * N_RES, 256>>>(pos, pb, pbmask, aamask, aatype, lw, lb, out);
}

// round 4
// speedup vs baseline: 1.0685x; 1.0685x over previous
#include <cuda_runtime.h>
#include <cuda_fp16.h>
#include <cstdint>

#define N_TEMPL 4
#define N_RES   768
#define NCH     64
#define NGCOLS  62   // gather table: cols 0..38 = bins, 39 = zero (no bin), 40..61 = aa_j

// smem: Wt_h 62*64*2 = 7936 B + sData 768*16 = 12288 B + consts ≈ 20.3 KB
__global__ __launch_bounds__(256) void tpe_kernel(
    const float* __restrict__ pos,      // [T,768,37,3]
    const float* __restrict__ pb,       // [T,768,3]
    const float* __restrict__ pbm,      // [T,768]
    const float* __restrict__ aam,      // [T,768,37]
    const int*   __restrict__ aatype,   // [T,768]
    const float* __restrict__ lw,       // [64,88] row-major (o-major)
    const float* __restrict__ lb,       // [64]
    float* __restrict__ out)            // [T,768,768,64]
{
    __shared__ alignas(16) __half Wt_h[NGCOLS * NCH];
    __shared__ float4 sData[N_RES];   // uvx, uvy, uvz, packed(bin | aaCol<<6 | pb<<12 | fm<<13)
    __shared__ float  sM[9];
    __shared__ float  sCa[3];
    __shared__ float  sPb[3];
    __shared__ float  sPbmI;
    __shared__ float  sFmI;
    __shared__ int    sAaI;

    const float EPS = 1e-6f;
    const int t = blockIdx.x / N_RES;
    const int i = blockIdx.x % N_RES;
    const int tid = threadIdx.x;

    // ---- Phase 0: stage fp16 gather table (transposed) + build rigid frame ----
    // Wt_h[c*64+o] = lw[o*88+c] for c in 0..38 (bins) and 40..61 (aa_j); col 39 = 0.
    for (int idx = tid; idx < NGCOLS * NCH; idx += 256) {
        int c = idx >> 6, o = idx & 63;
        float v = (c == 39) ? 0.0f : lw[o * 88 + c];
        Wt_h[idx] = __float2half_rn(v);
    }

    if (tid == 0) {
        const float* pr = pos + ((size_t)(t * N_RES + i) * 37) * 3;
        float nx0 = pr[0], nx1 = pr[1], nx2 = pr[2];     // N
        float ca0 = pr[3], ca1 = pr[4], ca2 = pr[5];     // CA
        float cc0 = pr[6], cc1 = pr[7], cc2 = pr[8];     // C
        float n0 = nx0 - ca0, n1 = nx1 - ca1, n2 = nx2 - ca2;
        float c0 = cc0 - ca0, c1v = cc1 - ca1, c2v = cc2 - ca2;

        float d2xy = c0 * c0 + c1v * c1v;
        float norm1 = sqrtf(EPS + d2xy);
        float s1 = -c1v / norm1, co1 = c0 / norm1;
        float norm2 = sqrtf(EPS + d2xy + c2v * c2v);
        float s2 = c2v / norm2, co2 = sqrtf(d2xy) / norm2;

        float r00 = co2 * co1, r01 = -co2 * s1, r02 = s2;
        float r10 = s1,        r11 = co1,       r12 = 0.0f;
        float r20 = -s2 * co1, r21 = s2 * s1,   r22 = co2;

        float nyp = r10 * n0 + r11 * n1 + r12 * n2;
        float nzp = r20 * n0 + r21 * n1 + r22 * n2;
        float norm3 = sqrtf(EPS + nyp * nyp + nzp * nzp);
        float sn = -nzp / norm3, cn = nyp / norm3;

        sM[0] = r00; sM[1] = r01; sM[2] = r02;
        sM[3] = cn * r10 - sn * r20; sM[4] = cn * r11 - sn * r21; sM[5] = cn * r12 - sn * r22;
        sM[6] = sn * r10 + cn * r20; sM[7] = sn * r11 + cn * r21; sM[8] = sn * r12 + cn * r22;

        sCa[0] = ca0; sCa[1] = ca1; sCa[2] = ca2;
        const float* pbi = pb + (size_t)(t * N_RES + i) * 3;
        sPb[0] = pbi[0]; sPb[1] = pbi[1]; sPb[2] = pbi[2];
        sPbmI = pbm[t * N_RES + i];
        const float* ami = aam + (size_t)(t * N_RES + i) * 37;
        sFmI = ami[0] * ami[1] * ami[2];
        sAaI = aatype[t * N_RES + i];
    }
    __syncthreads();

    // ---------------- Phase 1: per-j scalars ----------------------------------
    {
        const float m0 = sM[0], m1 = sM[1], m2 = sM[2];
        const float m3 = sM[3], m4 = sM[4], m5 = sM[5];
        const float m6 = sM[6], m7 = sM[7], m8 = sM[8];
        const float cai0 = sCa[0], cai1 = sCa[1], cai2 = sCa[2];
        const float pbi0 = sPb[0], pbi1 = sPb[1], pbi2 = sPb[2];
        const float pbmi = sPbmI, fmi = sFmI;

        for (int j = tid; j < N_RES; j += 256) {
            // distogram bin (match reference FP ordering)
            const float* pbj = pb + (size_t)(t * N_RES + j) * 3;
            float dx = __fadd_rn(pbi0, -pbj[0]);
            float dy = __fadd_rn(pbi1, -pbj[1]);
            float dz = __fadd_rn(pbi2, -pbj[2]);
            float dsq = __fadd_rn(__fadd_rn(__fmul_rn(dx, dx), __fmul_rn(dy, dy)),
                                  __fmul_rn(dz, dz));
            int k = (int)floorf((sqrtf(dsq) - 3.25f) * 0.8f);
            k = min(max(k, -1), 38);
            int bin = -1;
            int clo = max(k - 1, 0), chi = min(k + 1, 38);
            #pragma unroll
            for (int c = 0; c < 3; ++c) {
                int cand = clo + c;
                if (cand > chi) break;
                float lbv = 3.25f + (float)cand * 1.25f;  lbv = lbv * lbv;
                float ubv = (cand == 38) ? 1e8f
                           : (3.25f + (float)(cand + 1) * 1.25f) *
                             (3.25f + (float)(cand + 1) * 1.25f);
                if (dsq > lbv && dsq < ubv) { bin = cand; break; }
            }

            // rigid vec + unit vector
            const float* pj = pos + ((size_t)(t * N_RES + j) * 37 + 1) * 3; // CA_j
            float ddx = pj[0] - cai0, ddy = pj[1] - cai1, ddz = pj[2] - cai2;
            float rvx = m0 * ddx + m1 * ddy + m2 * ddz;
            float rvy = m3 * ddx + m4 * ddy + m5 * ddz;
            float rvz = m6 * ddx + m7 * ddy + m8 * ddz;
            float inv = 1.0f / sqrtf(EPS + (rvx * rvx + rvy * rvy + rvz * rvz));
            float uvx = rvx * inv, uvy = rvy * inv, uvz = rvz * inv;

            const float* amj = aam + (size_t)(t * N_RES + j) * 37;
            float fm2 = fmi * (amj[0] * amj[1] * amj[2]);
            float pb2 = pbmi * pbm[t * N_RES + j];

            int binCol = (bin < 0) ? 39 : bin;
            int aaCol  = 40 + aatype[t * N_RES + j];
            int packed = binCol | (aaCol << 6);
            if (pb2 != 0.0f) packed |= 1 << 12;
            if (fm2 != 0.0f) packed |= 1 << 13;
            sData[j] = make_float4(uvx, uvy, uvz, __int_as_float(packed));
        }
    }
    __syncthreads();

    // ---------------- Phase 2: 16 threads x 4 channels per j ------------------
    const int oq = tid & 15;          // channel quad
    const int jl = tid >> 4;          // 16 j's per iteration
    const int ob = oq * 4;

    // Dense per-thread constants in exact fp32 (direct cached loads)
    float4 rowb, w39v, w84v, w85v, w86v, bv;
    {
        int ai = sAaI;
        rowb = make_float4(
            __ldg(&lw[(ob + 0) * 88 + 62 + ai]) + __ldg(&lw[(ob + 0) * 88 + 87]),
            __ldg(&lw[(ob + 1) * 88 + 62 + ai]) + __ldg(&lw[(ob + 1) * 88 + 87]),
            __ldg(&lw[(ob + 2) * 88 + 62 + ai]) + __ldg(&lw[(ob + 2) * 88 + 87]),
            __ldg(&lw[(ob + 3) * 88 + 62 + ai]) + __ldg(&lw[(ob + 3) * 88 + 87]));
        w39v = make_float4(__ldg(&lw[(ob + 0) * 88 + 39]), __ldg(&lw[(ob + 1) * 88 + 39]),
                           __ldg(&lw[(ob + 2) * 88 + 39]), __ldg(&lw[(ob + 3) * 88 + 39]));
        w84v = make_float4(__ldg(&lw[(ob + 0) * 88 + 84]), __ldg(&lw[(ob + 1) * 88 + 84]),
                           __ldg(&lw[(ob + 2) * 88 + 84]), __ldg(&lw[(ob + 3) * 88 + 84]));
        w85v = make_float4(__ldg(&lw[(ob + 0) * 88 + 85]), __ldg(&lw[(ob + 1) * 88 + 85]),
                           __ldg(&lw[(ob + 2) * 88 + 85]), __ldg(&lw[(ob + 3) * 88 + 85]));
        w86v = make_float4(__ldg(&lw[(ob + 0) * 88 + 86]), __ldg(&lw[(ob + 1) * 88 + 86]),
                           __ldg(&lw[(ob + 2) * 88 + 86]), __ldg(&lw[(ob + 3) * 88 + 86]));
        bv   = *(const float4*)&lb[ob];
    }

    float* orow = out + ((size_t)(t * N_RES + i) * N_RES) * NCH;

    #pragma unroll 4
    for (int jb = 0; jb < N_RES; jb += 16) {
        int j = jb + jl;
        float4 d = sData[j];
        int p = __float_as_int(d.w);

        // Two fp16 gathers (8 B each), summed in half2, converted to float
        const __half2* gb = (const __half2*)&Wt_h[((p & 63) << 6) + ob];
        const __half2* ga = (const __half2*)&Wt_h[(((p >> 6) & 63) << 6) + ob];
        __half2 h0 = __hadd2(gb[0], ga[0]);
        __half2 h1 = __hadd2(gb[1], ga[1]);
        float2 c01 = __half22float2(h0);
        float2 c23 = __half22float2(h1);

        float pb2f = (p & (1 << 12)) ? 1.0f : 0.0f;
        float fm2f = (p & (1 << 13)) ? 1.0f : 0.0f;

        float4 r;
        {
            float s = rowb.x + c01.x;
            s = fmaf(pb2f, w39v.x, s);
            s = fmaf(d.x, w84v.x, s);
            s = fmaf(d.y, w85v.x, s);
            s = fmaf(d.z, w86v.x, s);
            r.x = fmaf(fm2f, s, bv.x);
        }
        {
            float s = rowb.y + c01.y;
            s = fmaf(pb2f, w39v.y, s);
            s = fmaf(d.x, w84v.y, s);
            s = fmaf(d.y, w85v.y, s);
            s = fmaf(d.z, w86v.y, s);
            r.y = fmaf(fm2f, s, bv.y);
        }
        {
            float s = rowb.z + c23.x;
            s = fmaf(pb2f, w39v.z, s);
            s = fmaf(d.x, w84v.z, s);
            s = fmaf(d.y, w85v.z, s);
            s = fmaf(d.z, w86v.z, s);
            r.z = fmaf(fm2f, s, bv.z);
        }
        {
            float s = rowb.w + c23.y;
            s = fmaf(pb2f, w39v.w, s);
            s = fmaf(d.x, w84v.w, s);
            s = fmaf(d.y, w85v.w, s);
            s = fmaf(d.z, w86v.w, s);
            r.w = fmaf(fm2f, s, bv.w);
        }

        *(float4*)&orow[(size_t)j * NCH + ob] = r;
    }
}

extern "C" void kernel_launch(void* const* d_in, const int* in_sizes, int n_in,
                              void* d_out, int out_size) {
    const float* pos    = (const float*)d_in[0];  // [4,768,37,3]
    const float* pb     = (const float*)d_in[1];  // [4,768,3]
    const float* pbmask = (const float*)d_in[2];  // [4,768]
    const float* aamask = (const float*)d_in[3];  // [4,768,37]
    const int*   aatype = (const int*)  d_in[4];  // [4,768]
    const float* lw     = (const float*)d_in[5];  // [64,88]
    const float* lb     = (const float*)d_in[6];  // [64]
    float* out = (float*)d_out;

    tpe_kernel<<<N_TEMPL * N_RES, 256>>>(pos, pb, pbmask, aamask, aatype, lw, lb, out);
}